// round 10
// baseline (speedup 1.0000x reference)
#include <cuda_runtime.h>
#include <math.h>

// ---------------- problem constants ----------------
#define Bq     64
#define Nq     128
#define NTOT   8192          // B*N
#define RINq   32
#define ROUTq  64
#define DEMBq  64
#define FINq   64
#define FEq    16
#define NEDGE  65536
#define RFCNT  (NTOT*RINq)   // 262144
#define M_ELEMS (Bq*Nq*Nq)   // 1048576

// ---------------- scratch (device globals; no runtime alloc) ----------------
__device__ float g_h_r [NTOT*DEMBq];
__device__ float g_h_p [NTOT*DEMBq];
__device__ float g_agg [NTOT*64];
__device__ float g_Mhat[M_ELEMS];
__device__ float g_M   [M_ELEMS];
__device__ float g_rf_r[NTOT*RINq];
__device__ float g_rf_p[NTOT*RINq];
__device__ float g_o   [NTOT*64];
__device__ float g_a_r [NTOT*64];
__device__ float g_a_p [NTOT*64];

// ---------------- utility kernels ----------------
__global__ void zero_kernel(float* __restrict__ p, int n)
{
    int i = blockIdx.x * blockDim.x + threadIdx.x;
    if (i < n) p[i] = 0.0f;
}

// ---------------- edge message kernel ----------------
// msg = relu(x[src] @ Wm + ef @ We); atomicAdd into agg[dst].
// One warp per edge (grid-strided). Wm/We in SMEM as float2 (cols j, j+32).
template<int FIN_T>
__global__ void edge_kernel(const float* __restrict__ x,
                            const int*   __restrict__ ei,   // [2, NEDGE]
                            const float* __restrict__ ef,   // [NEDGE, 16]
                            const float* __restrict__ Wm,   // [FIN_T, 64]
                            const float* __restrict__ We,   // [16, 64]
                            float*       __restrict__ agg)  // [NTOT, 64]
{
    __shared__ float2 sWm[FIN_T * 32];
    __shared__ float2 sWe[FEq * 32];
    for (int i = threadIdx.x; i < FIN_T * 32; i += blockDim.x) {
        int k = i >> 5, j = i & 31;
        sWm[i] = make_float2(Wm[k*64 + j], Wm[k*64 + 32 + j]);
    }
    for (int i = threadIdx.x; i < FEq * 32; i += blockDim.x) {
        int c = i >> 5, j = i & 31;
        sWe[i] = make_float2(We[c*64 + j], We[c*64 + 32 + j]);
    }
    __syncthreads();

    const int lane  = threadIdx.x & 31;
    const int warp  = threadIdx.x >> 5;
    const int nwarp = blockDim.x >> 5;
    const int* __restrict__ srcA = ei;
    const int* __restrict__ dstA = ei + NEDGE;

    for (int e = blockIdx.x * nwarp + warp; e < NEDGE; e += gridDim.x * nwarp) {
        int s = __ldg(srcA + e);
        int d = __ldg(dstA + e);
        float xv0 = __ldg(x + s*FIN_T + lane);
        float xv1 = (FIN_T > 32) ? __ldg(x + s*FIN_T + 32 + lane) : 0.0f;
        float efv = __ldg(ef + e*FEq + (lane & 15));
        float acc0 = 0.0f, acc1 = 0.0f;
        #pragma unroll
        for (int k = 0; k < FIN_T; ++k) {
            float xk = __shfl_sync(0xffffffffu, (k < 32) ? xv0 : xv1, k & 31);
            float2 w = sWm[k*32 + lane];
            acc0 = fmaf(xk, w.x, acc0);
            acc1 = fmaf(xk, w.y, acc1);
        }
        #pragma unroll
        for (int c = 0; c < FEq; ++c) {
            float ec = __shfl_sync(0xffffffffu, efv, c);
            float2 w = sWe[c*32 + lane];
            acc0 = fmaf(ec, w.x, acc0);
            acc1 = fmaf(ec, w.y, acc1);
        }
        acc0 = fmaxf(acc0, 0.0f);
        acc1 = fmaxf(acc1, 0.0f);
        atomicAdd(agg + d*64 + lane,      acc0);
        atomicAdd(agg + d*64 + 32 + lane, acc1);
    }
}

// ---------------- node kernel ----------------
// RELU_AGG=true : out = relu(x @ W + agg + bias)
// RELU_AGG=false: out = x @ W + (bias if non-null)
template<int FIN_T, bool RELU_AGG>
__global__ void node_kernel(const float* __restrict__ x,     // [NTOT, FIN_T]
                            const float* __restrict__ W,     // [FIN_T, 64]
                            const float* __restrict__ bias,  // [64] or null
                            const float* __restrict__ agg,   // [NTOT, 64] or null
                            float*       __restrict__ out)   // [NTOT, 64]
{
    __shared__ float2 sW[FIN_T * 32];
    __shared__ float  sb[64];
    for (int i = threadIdx.x; i < FIN_T * 32; i += blockDim.x) {
        int k = i >> 5, j = i & 31;
        sW[i] = make_float2(W[k*64 + j], W[k*64 + 32 + j]);
    }
    if (threadIdx.x < 64) sb[threadIdx.x] = bias ? bias[threadIdx.x] : 0.0f;
    __syncthreads();

    const int lane  = threadIdx.x & 31;
    const int warp  = threadIdx.x >> 5;
    const int nwarp = blockDim.x >> 5;

    for (int n = blockIdx.x * nwarp + warp; n < NTOT; n += gridDim.x * nwarp) {
        float xv0 = __ldg(x + n*FIN_T + lane);
        float xv1 = (FIN_T > 32) ? __ldg(x + n*FIN_T + 32 + lane) : 0.0f;
        float acc0 = sb[lane], acc1 = sb[lane + 32];
        #pragma unroll
        for (int k = 0; k < FIN_T; ++k) {
            float xk = __shfl_sync(0xffffffffu, (k < 32) ? xv0 : xv1, k & 31);
            float2 w = sW[k*32 + lane];
            acc0 = fmaf(xk, w.x, acc0);
            acc1 = fmaf(xk, w.y, acc1);
        }
        if (RELU_AGG) {
            acc0 = fmaxf(acc0 + agg[n*64 + lane],      0.0f);
            acc1 = fmaxf(acc1 + agg[n*64 + 32 + lane], 0.0f);
        }
        out[n*64 + lane]      = acc0;
        out[n*64 + 32 + lane] = acc1;
    }
}

// ---------------- M_hat = h_r @ h_p^T per batch ----------------
__global__ void mhat_kernel(const float* __restrict__ hr,
                            const float* __restrict__ hp,
                            float* __restrict__ Mhat)
{
    __shared__ float sHp[Nq * DEMBq];   // 32 KB
    int b = blockIdx.x;
    const float* hpb = hp + b * Nq * DEMBq;
    for (int i = threadIdx.x; i < Nq * DEMBq; i += blockDim.x) sHp[i] = hpb[i];
    __syncthreads();

    int r = threadIdx.x;                 // 128 threads, one row each
    float xr[DEMBq];
    const float* hrr = hr + (b*Nq + r) * DEMBq;
    #pragma unroll
    for (int k = 0; k < DEMBq; ++k) xr[k] = hrr[k];
    float* mrow = Mhat + (b*Nq + r) * Nq;
    for (int p = 0; p < Nq; ++p) {
        float acc = 0.0f;
        #pragma unroll
        for (int k = 0; k < DEMBq; ++k) acc = fmaf(xr[k], sHp[p*DEMBq + k], acc);
        mrow[p] = acc;
    }
}

// ---------------- row softmax (warp per row of 128) ----------------
__global__ void softmax_kernel(const float* __restrict__ src,
                               float* __restrict__ dstA,
                               float* __restrict__ dstB)
{
    int row  = blockIdx.x * (blockDim.x >> 5) + (threadIdx.x >> 5);
    int lane = threadIdx.x & 31;
    if (row >= NTOT) return;
    const float* s = src + row * Nq;
    float v0 = s[lane], v1 = s[lane+32], v2 = s[lane+64], v3 = s[lane+96];
    float mx = fmaxf(fmaxf(v0, v1), fmaxf(v2, v3));
    #pragma unroll
    for (int o = 16; o > 0; o >>= 1) mx = fmaxf(mx, __shfl_xor_sync(0xffffffffu, mx, o));
    v0 = expf(v0 - mx); v1 = expf(v1 - mx); v2 = expf(v2 - mx); v3 = expf(v3 - mx);
    float sm = v0 + v1 + v2 + v3;
    #pragma unroll
    for (int o = 16; o > 0; o >>= 1) sm += __shfl_xor_sync(0xffffffffu, sm, o);
    float inv = 1.0f / sm;
    float* dA = dstA + row * Nq;
    dA[lane] = v0*inv; dA[lane+32] = v1*inv; dA[lane+64] = v2*inv; dA[lane+96] = v3*inv;
    if (dstB) {
        float* dB = dstB + row * Nq;
        dB[lane] = v0*inv; dB[lane+32] = v1*inv; dB[lane+64] = v2*inv; dB[lane+96] = v3*inv;
    }
}

// ---------------- threefry + jax.random.normal reproduction ----------------
__device__ __forceinline__ unsigned rotl32d(unsigned v, int s) { return (v << s) | (v >> (32 - s)); }

// XLA's f32 ErfInv (Giles polynomial) — matches reference bit-closely.
__device__ __forceinline__ float erfinv_xla(float x)
{
    float w = -log1pf(-x * x);
    float p;
    if (w < 5.0f) {
        w = w - 2.5f;
        p = 2.81022636e-08f;
        p = fmaf(p, w, 3.43273939e-07f);
        p = fmaf(p, w, -3.5233877e-06f);
        p = fmaf(p, w, -4.39150654e-06f);
        p = fmaf(p, w, 0.00021858087f);
        p = fmaf(p, w, -0.00125372503f);
        p = fmaf(p, w, -0.00417768164f);
        p = fmaf(p, w, 0.246640727f);
        p = fmaf(p, w, 1.50140941f);
    } else {
        w = sqrtf(w) - 3.0f;
        p = -0.000200214257f;
        p = fmaf(p, w, 0.000100950558f);
        p = fmaf(p, w, 0.00134934322f);
        p = fmaf(p, w, -0.00367342844f);
        p = fmaf(p, w, 0.00573950773f);
        p = fmaf(p, w, -0.0076224613f);
        p = fmaf(p, w, 0.00943887047f);
        p = fmaf(p, w, 1.00167406f);
        p = fmaf(p, w, 2.83297682f);
    }
    return p * x;
}

__device__ __forceinline__ float bits_to_normal(unsigned w)
{
    const float LO = -0.99999994f;          // nextafter(-1, 0)
    const float SCALE = 1.0f - LO;          // 1.99999994f
    float u = __uint_as_float((w >> 9) | 0x3f800000u) - 1.0f;  // [0,1)
    float a = fmaxf(fmaf(u, SCALE, LO), LO);
    return 1.41421356237f * erfinv_xla(a);  // sqrt(2) * erfinv
}

// Partitionable threefry (jax_threefry_partitionable=True, modern JAX default):
// element i gets counter pair (hi, lo) = (0, i); with x64 disabled, the 32-bit
// random word is the XOR of the two threefry output lanes:
//   bits1, bits2 = threefry2x32(k1, k2, counts_hi, counts_lo)
//   bits = convert_element_type(bits1 ^ bits2, uint32)
__global__ void rfgen_kernel(float* __restrict__ rf, unsigned k0, unsigned k1)
{
    int i = blockIdx.x * blockDim.x + threadIdx.x;
    if (i >= RFCNT) return;
    unsigned ks2 = k0 ^ k1 ^ 0x1BD11BDAu;
    unsigned x0 = k0;                 // hi counter (0) + k0
    unsigned x1 = (unsigned)i + k1;   // lo counter (i) + k1
    #define TFR(r) { x0 += x1; x1 = rotl32d(x1, r); x1 ^= x0; }
    TFR(13) TFR(15) TFR(26) TFR(6)   x0 += k1;  x1 += ks2 + 1u;
    TFR(17) TFR(29) TFR(16) TFR(24)  x0 += ks2; x1 += k0 + 2u;
    TFR(13) TFR(15) TFR(26) TFR(6)   x0 += k0;  x1 += k1 + 3u;
    TFR(17) TFR(29) TFR(16) TFR(24)  x0 += k1;  x1 += ks2 + 4u;
    TFR(13) TFR(15) TFR(26) TFR(6)   x0 += ks2; x1 += k0 + 5u;
    #undef TFR
    rf[i] = bits_to_normal(x0 ^ x1);
}

// ---------------- rf_p[b,p,:] = sum_r M[b,r,p] * rf_r[b,r,:] ----------------
__global__ void rfp_kernel(const float* __restrict__ M,
                           const float* __restrict__ rfr,
                           float* __restrict__ rfp)
{
    __shared__ float sR[Nq * RINq];   // 16 KB
    int b = blockIdx.x;
    const float* Mb = M + b * Nq * Nq;
    const float* rb = rfr + b * Nq * RINq;
    for (int i = threadIdx.x; i < Nq * RINq; i += blockDim.x) sR[i] = rb[i];
    __syncthreads();

    int p = threadIdx.x;              // 128 threads
    float acc[RINq];
    #pragma unroll
    for (int i = 0; i < RINq; ++i) acc[i] = 0.0f;
    for (int r = 0; r < Nq; ++r) {
        float m = Mb[r * Nq + p];     // coalesced across threads
        #pragma unroll
        for (int i = 0; i < RINq; ++i) acc[i] = fmaf(m, sR[r*RINq + i], acc[i]);
    }
    float* ob = rfp + (b*Nq + p) * RINq;
    #pragma unroll
    for (int i = 0; i < RINq; ++i) ob[i] = acc[i];
}

// ---------------- consensus update ----------------
// Mhat[b,r,p] += sum_k relu(a_r[b,r,k] - a_p[b,p,k]) * W2[k] + b2
// (b1 pre-folded into a_r). a_p stored transposed in SMEM for conflict-free reads.
__global__ void upd_kernel(const float* __restrict__ ar,
                           const float* __restrict__ ap,
                           const float* __restrict__ W2,
                           const float* __restrict__ b2p,
                           float* __restrict__ Mhat)
{
    extern __shared__ float smem[];
    float* sAr  = smem;                 // [r][k]  N*ROUT
    float* sApT = smem + Nq * ROUTq;    // [k][p]  ROUT*N
    __shared__ float sW2[ROUTq];

    int b = blockIdx.x;
    const float* arb = ar + b * Nq * ROUTq;
    const float* apb = ap + b * Nq * ROUTq;
    for (int i = threadIdx.x; i < Nq * ROUTq; i += blockDim.x) {
        sAr[i] = arb[i];
        int p = i & (Nq - 1);
        int k = i >> 7;
        sApT[k*Nq + p] = apb[p*ROUTq + k];
    }
    if (threadIdx.x < ROUTq) sW2[threadIdx.x] = W2[threadIdx.x];
    __syncthreads();

    float b2 = b2p[0];
    int lane = threadIdx.x & 31;
    int warp = threadIdx.x >> 5;        // 8 warps, 16 rows each

    for (int rr = 0; rr < 16; ++rr) {
        int r = warp * 16 + rr;
        const float* arow = sAr + r * ROUTq;
        float acc0 = 0.f, acc1 = 0.f, acc2 = 0.f, acc3 = 0.f;
        #pragma unroll 8
        for (int k = 0; k < ROUTq; ++k) {
            float av = arow[k];
            float w  = sW2[k];
            const float* aprow = sApT + k * Nq;
            acc0 = fmaf(fmaxf(av - aprow[lane     ], 0.f), w, acc0);
            acc1 = fmaf(fmaxf(av - aprow[lane + 32], 0.f), w, acc1);
            acc2 = fmaf(fmaxf(av - aprow[lane + 64], 0.f), w, acc2);
            acc3 = fmaf(fmaxf(av - aprow[lane + 96], 0.f), w, acc3);
        }
        float* mr = Mhat + (b*Nq + r) * Nq;
        mr[lane]      += acc0 + b2;
        mr[lane + 32] += acc1 + b2;
        mr[lane + 64] += acc2 + b2;
        mr[lane + 96] += acc3 + b2;
    }
}

// ---------------- host threefry (key fold_in; classic 2-element scheme) ----------------
static void host_threefry(unsigned k0, unsigned k1, unsigned c0, unsigned c1,
                          unsigned* o0, unsigned* o1)
{
    unsigned ks2 = k0 ^ k1 ^ 0x1BD11BDAu;
    unsigned x0 = c0 + k0, x1 = c1 + k1;
    #define HTFR(r) { x0 += x1; x1 = (x1 << (r)) | (x1 >> (32 - (r))); x1 ^= x0; }
    HTFR(13) HTFR(15) HTFR(26) HTFR(6)   x0 += k1;  x1 += ks2 + 1u;
    HTFR(17) HTFR(29) HTFR(16) HTFR(24)  x0 += ks2; x1 += k0 + 2u;
    HTFR(13) HTFR(15) HTFR(26) HTFR(6)   x0 += k0;  x1 += k1 + 3u;
    HTFR(17) HTFR(29) HTFR(16) HTFR(24)  x0 += k1;  x1 += ks2 + 4u;
    HTFR(13) HTFR(15) HTFR(26) HTFR(6)   x0 += ks2; x1 += k0 + 5u;
    #undef HTFR
    *o0 = x0; *o1 = x1;
}

// ---------------- orchestration ----------------
extern "C" void kernel_launch(void* const* d_in, const int* in_sizes, int n_in,
                              void* d_out, int out_size)
{
    const float* x_r   = (const float*)d_in[0];
    const int*   ei_r  = (const int*)  d_in[1];
    const float* ef_r  = (const float*)d_in[2];
    const float* x_p   = (const float*)d_in[3];
    const int*   ei_p  = (const int*)  d_in[4];
    const float* ef_p  = (const float*)d_in[5];
    // d_in[6], d_in[7]: r_mask, p_mask — all True, unused
    const float* g1_Ws = (const float*)d_in[8];
    const float* g1_Wm = (const float*)d_in[9];
    const float* g1_We = (const float*)d_in[10];
    const float* g1_b  = (const float*)d_in[11];
    const float* g2_Ws = (const float*)d_in[12];
    const float* g2_Wm = (const float*)d_in[13];
    const float* g2_We = (const float*)d_in[14];
    const float* g2_b  = (const float*)d_in[15];
    const float* W1    = (const float*)d_in[16];
    const float* b1    = (const float*)d_in[17];
    const float* W2    = (const float*)d_in[18];
    const float* b2    = (const float*)d_in[19];
    float* out = (float*)d_out;

    float *h_r, *h_p, *agg, *Mhat, *M, *rf_r, *rf_p, *o, *a_r, *a_p;
    cudaGetSymbolAddress((void**)&h_r,  g_h_r);
    cudaGetSymbolAddress((void**)&h_p,  g_h_p);
    cudaGetSymbolAddress((void**)&agg,  g_agg);
    cudaGetSymbolAddress((void**)&Mhat, g_Mhat);
    cudaGetSymbolAddress((void**)&M,    g_M);
    cudaGetSymbolAddress((void**)&rf_r, g_rf_r);
    cudaGetSymbolAddress((void**)&rf_p, g_rf_p);
    cudaGetSymbolAddress((void**)&o,    g_o);
    cudaGetSymbolAddress((void**)&a_r,  g_a_r);
    cudaGetSymbolAddress((void**)&a_p,  g_a_p);

    cudaFuncSetAttribute(upd_kernel, cudaFuncAttributeMaxDynamicSharedMemorySize, 2*Nq*ROUTq*4);

    // ---- gnn_1 on r and p graphs -> h_r, h_p ----
    zero_kernel<<<2048, 256>>>(agg, NTOT*64);
    edge_kernel<64><<<1024, 256>>>(x_r, ei_r, ef_r, g1_Wm, g1_We, agg);
    node_kernel<64, true><<<256, 256>>>(x_r, g1_Ws, g1_b, agg, h_r);

    zero_kernel<<<2048, 256>>>(agg, NTOT*64);
    edge_kernel<64><<<1024, 256>>>(x_p, ei_p, ef_p, g1_Wm, g1_We, agg);
    node_kernel<64, true><<<256, 256>>>(x_p, g1_Ws, g1_b, agg, h_p);

    // ---- M_hat = h_r @ h_p^T (per batch) ----
    mhat_kernel<<<Bq, 128>>>(h_r, h_p, Mhat);

    // ---- consensus iterations ----
    for (int it = 0; it < 3; ++it) {
        // M = softmax(M_hat); iter 0 also writes M_0 output
        softmax_kernel<<<1024, 256>>>(Mhat, M, (it == 0) ? out : (float*)nullptr);

        // rf_r = jax.random.normal(fold_in(key(42), it), (B,N,RIN))
        unsigned k0, k1;
        host_threefry(0u, 42u, 0u, (unsigned)it, &k0, &k1);
        rfgen_kernel<<<RFCNT/256, 256>>>(rf_r, k0, k1);

        // rf_p = M^T @ rf_r
        rfp_kernel<<<Bq, 128>>>(M, rf_r, rf_p);

        // o_r = gnn2(rf_r, r-graph); a_r = o_r@W1 + b1
        zero_kernel<<<2048, 256>>>(agg, NTOT*64);
        edge_kernel<32><<<1024, 256>>>(rf_r, ei_r, ef_r, g2_Wm, g2_We, agg);
        node_kernel<32, true><<<256, 256>>>(rf_r, g2_Ws, g2_b, agg, o);
        node_kernel<64, false><<<256, 256>>>(o, W1, b1, nullptr, a_r);

        // o_p = gnn2(rf_p, p-graph); a_p = o_p@W1
        zero_kernel<<<2048, 256>>>(agg, NTOT*64);
        edge_kernel<32><<<1024, 256>>>(rf_p, ei_p, ef_p, g2_Wm, g2_We, agg);
        node_kernel<32, true><<<256, 256>>>(rf_p, g2_Ws, g2_b, agg, o);
        node_kernel<64, false><<<256, 256>>>(o, W1, nullptr, nullptr, a_p);

        // M_hat += relu(a_r[r]-a_p[p]) @ W2 + b2
        upd_kernel<<<Bq, 256, 2*Nq*ROUTq*4>>>(a_r, a_p, W2, b2, Mhat);
    }

    // ---- M_T output ----
    softmax_kernel<<<1024, 256>>>(Mhat, out + M_ELEMS, nullptr);
}

// round 15
// speedup vs baseline: 1.0023x; 1.0023x over previous
#include <cuda_runtime.h>
#include <math.h>

// ---------------- problem constants ----------------
#define Bq     64
#define Nq     128
#define NTOT   8192          // B*N
#define RINq   32
#define ROUTq  64
#define DEMBq  64
#define FINq   64
#define FEq    16
#define NEDGE  65536
#define RFCNT  (NTOT*RINq)   // 262144
#define M_ELEMS (Bq*Nq*Nq)   // 1048576

// ---------------- scratch (device globals; no runtime alloc) ----------------
__device__ float g_h_r [NTOT*DEMBq];
__device__ float g_h_p [NTOT*DEMBq];
__device__ float g_agg [NTOT*64];
__device__ float g_Mhat[M_ELEMS];
__device__ float g_M   [M_ELEMS];
__device__ float g_rf_r[NTOT*RINq];
__device__ float g_rf_p[NTOT*RINq];
__device__ float g_o   [NTOT*64];
__device__ float g_a_r [NTOT*64];
__device__ float g_a_p [NTOT*64];

// ---------------- utility kernels ----------------
__global__ void zero_kernel(float* __restrict__ p, int n)
{
    int i = blockIdx.x * blockDim.x + threadIdx.x;
    if (i < n) p[i] = 0.0f;
}

// ---------------- edge message kernel ----------------
// msg = relu(x[src] @ Wm + ef @ We); atomicAdd into agg[dst].
// One warp per edge (grid-strided). Wm/We in SMEM as float2 (cols j, j+32).
template<int FIN_T>
__global__ void edge_kernel(const float* __restrict__ x,
                            const int*   __restrict__ ei,   // [2, NEDGE]
                            const float* __restrict__ ef,   // [NEDGE, 16]
                            const float* __restrict__ Wm,   // [FIN_T, 64]
                            const float* __restrict__ We,   // [16, 64]
                            float*       __restrict__ agg)  // [NTOT, 64]
{
    __shared__ float2 sWm[FIN_T * 32];
    __shared__ float2 sWe[FEq * 32];
    for (int i = threadIdx.x; i < FIN_T * 32; i += blockDim.x) {
        int k = i >> 5, j = i & 31;
        sWm[i] = make_float2(Wm[k*64 + j], Wm[k*64 + 32 + j]);
    }
    for (int i = threadIdx.x; i < FEq * 32; i += blockDim.x) {
        int c = i >> 5, j = i & 31;
        sWe[i] = make_float2(We[c*64 + j], We[c*64 + 32 + j]);
    }
    __syncthreads();

    const int lane  = threadIdx.x & 31;
    const int warp  = threadIdx.x >> 5;
    const int nwarp = blockDim.x >> 5;
    const int* __restrict__ srcA = ei;
    const int* __restrict__ dstA = ei + NEDGE;

    for (int e = blockIdx.x * nwarp + warp; e < NEDGE; e += gridDim.x * nwarp) {
        int s = __ldg(srcA + e);
        int d = __ldg(dstA + e);
        float xv0 = __ldg(x + s*FIN_T + lane);
        float xv1 = (FIN_T > 32) ? __ldg(x + s*FIN_T + 32 + lane) : 0.0f;
        float efv = __ldg(ef + e*FEq + (lane & 15));
        float acc0 = 0.0f, acc1 = 0.0f;
        #pragma unroll
        for (int k = 0; k < FIN_T; ++k) {
            float xk = __shfl_sync(0xffffffffu, (k < 32) ? xv0 : xv1, k & 31);
            float2 w = sWm[k*32 + lane];
            acc0 = fmaf(xk, w.x, acc0);
            acc1 = fmaf(xk, w.y, acc1);
        }
        #pragma unroll
        for (int c = 0; c < FEq; ++c) {
            float ec = __shfl_sync(0xffffffffu, efv, c);
            float2 w = sWe[c*32 + lane];
            acc0 = fmaf(ec, w.x, acc0);
            acc1 = fmaf(ec, w.y, acc1);
        }
        acc0 = fmaxf(acc0, 0.0f);
        acc1 = fmaxf(acc1, 0.0f);
        atomicAdd(agg + d*64 + lane,      acc0);
        atomicAdd(agg + d*64 + 32 + lane, acc1);
    }
}

// ---------------- node kernel ----------------
// RELU_AGG=true : out = relu(x @ W + agg + bias)
// RELU_AGG=false: out = x @ W + (bias if non-null)
template<int FIN_T, bool RELU_AGG>
__global__ void node_kernel(const float* __restrict__ x,     // [NTOT, FIN_T]
                            const float* __restrict__ W,     // [FIN_T, 64]
                            const float* __restrict__ bias,  // [64] or null
                            const float* __restrict__ agg,   // [NTOT, 64] or null
                            float*       __restrict__ out)   // [NTOT, 64]
{
    __shared__ float2 sW[FIN_T * 32];
    __shared__ float  sb[64];
    for (int i = threadIdx.x; i < FIN_T * 32; i += blockDim.x) {
        int k = i >> 5, j = i & 31;
        sW[i] = make_float2(W[k*64 + j], W[k*64 + 32 + j]);
    }
    if (threadIdx.x < 64) sb[threadIdx.x] = bias ? bias[threadIdx.x] : 0.0f;
    __syncthreads();

    const int lane  = threadIdx.x & 31;
    const int warp  = threadIdx.x >> 5;
    const int nwarp = blockDim.x >> 5;

    for (int n = blockIdx.x * nwarp + warp; n < NTOT; n += gridDim.x * nwarp) {
        float xv0 = __ldg(x + n*FIN_T + lane);
        float xv1 = (FIN_T > 32) ? __ldg(x + n*FIN_T + 32 + lane) : 0.0f;
        float acc0 = sb[lane], acc1 = sb[lane + 32];
        #pragma unroll
        for (int k = 0; k < FIN_T; ++k) {
            float xk = __shfl_sync(0xffffffffu, (k < 32) ? xv0 : xv1, k & 31);
            float2 w = sW[k*32 + lane];
            acc0 = fmaf(xk, w.x, acc0);
            acc1 = fmaf(xk, w.y, acc1);
        }
        if (RELU_AGG) {
            acc0 = fmaxf(acc0 + agg[n*64 + lane],      0.0f);
            acc1 = fmaxf(acc1 + agg[n*64 + 32 + lane], 0.0f);
        }
        out[n*64 + lane]      = acc0;
        out[n*64 + 32 + lane] = acc1;
    }
}

// ---------------- M_hat = h_r @ h_p^T per batch ----------------
__global__ void mhat_kernel(const float* __restrict__ hr,
                            const float* __restrict__ hp,
                            float* __restrict__ Mhat)
{
    __shared__ float sHp[Nq * DEMBq];   // 32 KB
    int b = blockIdx.x;
    const float* hpb = hp + b * Nq * DEMBq;
    for (int i = threadIdx.x; i < Nq * DEMBq; i += blockDim.x) sHp[i] = hpb[i];
    __syncthreads();

    int r = threadIdx.x;                 // 128 threads, one row each
    float xr[DEMBq];
    const float* hrr = hr + (b*Nq + r) * DEMBq;
    #pragma unroll
    for (int k = 0; k < DEMBq; ++k) xr[k] = hrr[k];
    float* mrow = Mhat + (b*Nq + r) * Nq;
    for (int p = 0; p < Nq; ++p) {
        float acc = 0.0f;
        #pragma unroll
        for (int k = 0; k < DEMBq; ++k) acc = fmaf(xr[k], sHp[p*DEMBq + k], acc);
        mrow[p] = acc;
    }
}

// ---------------- row softmax (warp per row of 128) ----------------
__global__ void softmax_kernel(const float* __restrict__ src,
                               float* __restrict__ dstA,
                               float* __restrict__ dstB)
{
    int row  = blockIdx.x * (blockDim.x >> 5) + (threadIdx.x >> 5);
    int lane = threadIdx.x & 31;
    if (row >= NTOT) return;
    const float* s = src + row * Nq;
    float v0 = s[lane], v1 = s[lane+32], v2 = s[lane+64], v3 = s[lane+96];
    float mx = fmaxf(fmaxf(v0, v1), fmaxf(v2, v3));
    #pragma unroll
    for (int o = 16; o > 0; o >>= 1) mx = fmaxf(mx, __shfl_xor_sync(0xffffffffu, mx, o));
    v0 = expf(v0 - mx); v1 = expf(v1 - mx); v2 = expf(v2 - mx); v3 = expf(v3 - mx);
    float sm = v0 + v1 + v2 + v3;
    #pragma unroll
    for (int o = 16; o > 0; o >>= 1) sm += __shfl_xor_sync(0xffffffffu, sm, o);
    float inv = 1.0f / sm;
    float* dA = dstA + row * Nq;
    dA[lane] = v0*inv; dA[lane+32] = v1*inv; dA[lane+64] = v2*inv; dA[lane+96] = v3*inv;
    if (dstB) {
        float* dB = dstB + row * Nq;
        dB[lane] = v0*inv; dB[lane+32] = v1*inv; dB[lane+64] = v2*inv; dB[lane+96] = v3*inv;
    }
}

// ---------------- threefry + jax.random.normal reproduction ----------------
__device__ __forceinline__ unsigned rotl32d(unsigned v, int s) { return (v << s) | (v >> (32 - s)); }

// XLA's f32 ErfInv (Giles polynomial) — matches reference bit-closely.
__device__ __forceinline__ float erfinv_xla(float x)
{
    float w = -log1pf(-x * x);
    float p;
    if (w < 5.0f) {
        w = w - 2.5f;
        p = 2.81022636e-08f;
        p = fmaf(p, w, 3.43273939e-07f);
        p = fmaf(p, w, -3.5233877e-06f);
        p = fmaf(p, w, -4.39150654e-06f);
        p = fmaf(p, w, 0.00021858087f);
        p = fmaf(p, w, -0.00125372503f);
        p = fmaf(p, w, -0.00417768164f);
        p = fmaf(p, w, 0.246640727f);
        p = fmaf(p, w, 1.50140941f);
    } else {
        w = sqrtf(w) - 3.0f;
        p = -0.000200214257f;
        p = fmaf(p, w, 0.000100950558f);
        p = fmaf(p, w, 0.00134934322f);
        p = fmaf(p, w, -0.00367342844f);
        p = fmaf(p, w, 0.00573950773f);
        p = fmaf(p, w, -0.0076224613f);
        p = fmaf(p, w, 0.00943887047f);
        p = fmaf(p, w, 1.00167406f);
        p = fmaf(p, w, 2.83297682f);
    }
    return p * x;
}

__device__ __forceinline__ float bits_to_normal(unsigned w)
{
    const float LO = -0.99999994f;          // nextafter(-1, 0)
    const float SCALE = 1.0f - LO;          // 1.99999994f
    float u = __uint_as_float((w >> 9) | 0x3f800000u) - 1.0f;  // [0,1)
    float a = fmaxf(fmaf(u, SCALE, LO), LO);
    return 1.41421356237f * erfinv_xla(a);  // sqrt(2) * erfinv
}

// Partitionable threefry (jax_threefry_partitionable=True, modern JAX default):
// element i gets counter pair (hi, lo) = (0, i); with x64 disabled, the 32-bit
// random word is the XOR of the two threefry output lanes:
//   bits1, bits2 = threefry2x32(k1, k2, counts_hi, counts_lo)
//   bits = convert_element_type(bits1 ^ bits2, uint32)
__global__ void rfgen_kernel(float* __restrict__ rf, unsigned k0, unsigned k1)
{
    int i = blockIdx.x * blockDim.x + threadIdx.x;
    if (i >= RFCNT) return;
    unsigned ks2 = k0 ^ k1 ^ 0x1BD11BDAu;
    unsigned x0 = k0;                 // hi counter (0) + k0
    unsigned x1 = (unsigned)i + k1;   // lo counter (i) + k1
    #define TFR(r) { x0 += x1; x1 = rotl32d(x1, r); x1 ^= x0; }
    TFR(13) TFR(15) TFR(26) TFR(6)   x0 += k1;  x1 += ks2 + 1u;
    TFR(17) TFR(29) TFR(16) TFR(24)  x0 += ks2; x1 += k0 + 2u;
    TFR(13) TFR(15) TFR(26) TFR(6)   x0 += k0;  x1 += k1 + 3u;
    TFR(17) TFR(29) TFR(16) TFR(24)  x0 += k1;  x1 += ks2 + 4u;
    TFR(13) TFR(15) TFR(26) TFR(6)   x0 += ks2; x1 += k0 + 5u;
    #undef TFR
    rf[i] = bits_to_normal(x0 ^ x1);
}

// ---------------- rf_p[b,p,:] = sum_r M[b,r,p] * rf_r[b,r,:] ----------------
__global__ void rfp_kernel(const float* __restrict__ M,
                           const float* __restrict__ rfr,
                           float* __restrict__ rfp)
{
    __shared__ float sR[Nq * RINq];   // 16 KB
    int b = blockIdx.x;
    const float* Mb = M + b * Nq * Nq;
    const float* rb = rfr + b * Nq * RINq;
    for (int i = threadIdx.x; i < Nq * RINq; i += blockDim.x) sR[i] = rb[i];
    __syncthreads();

    int p = threadIdx.x;              // 128 threads
    float acc[RINq];
    #pragma unroll
    for (int i = 0; i < RINq; ++i) acc[i] = 0.0f;
    for (int r = 0; r < Nq; ++r) {
        float m = Mb[r * Nq + p];     // coalesced across threads
        #pragma unroll
        for (int i = 0; i < RINq; ++i) acc[i] = fmaf(m, sR[r*RINq + i], acc[i]);
    }
    float* ob = rfp + (b*Nq + p) * RINq;
    #pragma unroll
    for (int i = 0; i < RINq; ++i) ob[i] = acc[i];
}

// ---------------- consensus update ----------------
// Mhat[b,r,p] += sum_k relu(a_r[b,r,k] - a_p[b,p,k]) * W2[k] + b2
// (b1 pre-folded into a_r). a_p stored transposed in SMEM for conflict-free reads.
__global__ void upd_kernel(const float* __restrict__ ar,
                           const float* __restrict__ ap,
                           const float* __restrict__ W2,
                           const float* __restrict__ b2p,
                           float* __restrict__ Mhat)
{
    extern __shared__ float smem[];
    float* sAr  = smem;                 // [r][k]  N*ROUT
    float* sApT = smem + Nq * ROUTq;    // [k][p]  ROUT*N
    __shared__ float sW2[ROUTq];

    int b = blockIdx.x;
    const float* arb = ar + b * Nq * ROUTq;
    const float* apb = ap + b * Nq * ROUTq;
    for (int i = threadIdx.x; i < Nq * ROUTq; i += blockDim.x) {
        sAr[i] = arb[i];
        int p = i & (Nq - 1);
        int k = i >> 7;
        sApT[k*Nq + p] = apb[p*ROUTq + k];
    }
    if (threadIdx.x < ROUTq) sW2[threadIdx.x] = W2[threadIdx.x];
    __syncthreads();

    float b2 = b2p[0];
    int lane = threadIdx.x & 31;
    int warp = threadIdx.x >> 5;        // 8 warps, 16 rows each

    for (int rr = 0; rr < 16; ++rr) {
        int r = warp * 16 + rr;
        const float* arow = sAr + r * ROUTq;
        float acc0 = 0.f, acc1 = 0.f, acc2 = 0.f, acc3 = 0.f;
        #pragma unroll 8
        for (int k = 0; k < ROUTq; ++k) {
            float av = arow[k];
            float w  = sW2[k];
            const float* aprow = sApT + k * Nq;
            acc0 = fmaf(fmaxf(av - aprow[lane     ], 0.f), w, acc0);
            acc1 = fmaf(fmaxf(av - aprow[lane + 32], 0.f), w, acc1);
            acc2 = fmaf(fmaxf(av - aprow[lane + 64], 0.f), w, acc2);
            acc3 = fmaf(fmaxf(av - aprow[lane + 96], 0.f), w, acc3);
        }
        float* mr = Mhat + (b*Nq + r) * Nq;
        mr[lane]      += acc0 + b2;
        mr[lane + 32] += acc1 + b2;
        mr[lane + 64] += acc2 + b2;
        mr[lane + 96] += acc3 + b2;
    }
}

// ---------------- host threefry (key fold_in; classic 2-element scheme) ----------------
static void host_threefry(unsigned k0, unsigned k1, unsigned c0, unsigned c1,
                          unsigned* o0, unsigned* o1)
{
    unsigned ks2 = k0 ^ k1 ^ 0x1BD11BDAu;
    unsigned x0 = c0 + k0, x1 = c1 + k1;
    #define HTFR(r) { x0 += x1; x1 = (x1 << (r)) | (x1 >> (32 - (r))); x1 ^= x0; }
    HTFR(13) HTFR(15) HTFR(26) HTFR(6)   x0 += k1;  x1 += ks2 + 1u;
    HTFR(17) HTFR(29) HTFR(16) HTFR(24)  x0 += ks2; x1 += k0 + 2u;
    HTFR(13) HTFR(15) HTFR(26) HTFR(6)   x0 += k0;  x1 += k1 + 3u;
    HTFR(17) HTFR(29) HTFR(16) HTFR(24)  x0 += k1;  x1 += ks2 + 4u;
    HTFR(13) HTFR(15) HTFR(26) HTFR(6)   x0 += ks2; x1 += k0 + 5u;
    #undef HTFR
    *o0 = x0; *o1 = x1;
}

// ---------------- orchestration ----------------
extern "C" void kernel_launch(void* const* d_in, const int* in_sizes, int n_in,
                              void* d_out, int out_size)
{
    const float* x_r   = (const float*)d_in[0];
    const int*   ei_r  = (const int*)  d_in[1];
    const float* ef_r  = (const float*)d_in[2];
    const float* x_p   = (const float*)d_in[3];
    const int*   ei_p  = (const int*)  d_in[4];
    const float* ef_p  = (const float*)d_in[5];
    // d_in[6], d_in[7]: r_mask, p_mask — all True, unused
    const float* g1_Ws = (const float*)d_in[8];
    const float* g1_Wm = (const float*)d_in[9];
    const float* g1_We = (const float*)d_in[10];
    const float* g1_b  = (const float*)d_in[11];
    const float* g2_Ws = (const float*)d_in[12];
    const float* g2_Wm = (const float*)d_in[13];
    const float* g2_We = (const float*)d_in[14];
    const float* g2_b  = (const float*)d_in[15];
    const float* W1    = (const float*)d_in[16];
    const float* b1    = (const float*)d_in[17];
    const float* W2    = (const float*)d_in[18];
    const float* b2    = (const float*)d_in[19];
    float* out = (float*)d_out;

    float *h_r, *h_p, *agg, *Mhat, *M, *rf_r, *rf_p, *o, *a_r, *a_p;
    cudaGetSymbolAddress((void**)&h_r,  g_h_r);
    cudaGetSymbolAddress((void**)&h_p,  g_h_p);
    cudaGetSymbolAddress((void**)&agg,  g_agg);
    cudaGetSymbolAddress((void**)&Mhat, g_Mhat);
    cudaGetSymbolAddress((void**)&M,    g_M);
    cudaGetSymbolAddress((void**)&rf_r, g_rf_r);
    cudaGetSymbolAddress((void**)&rf_p, g_rf_p);
    cudaGetSymbolAddress((void**)&o,    g_o);
    cudaGetSymbolAddress((void**)&a_r,  g_a_r);
    cudaGetSymbolAddress((void**)&a_p,  g_a_p);

    cudaFuncSetAttribute(upd_kernel, cudaFuncAttributeMaxDynamicSharedMemorySize, 2*Nq*ROUTq*4);

    // ---- gnn_1 on r and p graphs -> h_r, h_p ----
    zero_kernel<<<2048, 256>>>(agg, NTOT*64);
    edge_kernel<64><<<1024, 256>>>(x_r, ei_r, ef_r, g1_Wm, g1_We, agg);
    node_kernel<64, true><<<256, 256>>>(x_r, g1_Ws, g1_b, agg, h_r);

    zero_kernel<<<2048, 256>>>(agg, NTOT*64);
    edge_kernel<64><<<1024, 256>>>(x_p, ei_p, ef_p, g1_Wm, g1_We, agg);
    node_kernel<64, true><<<256, 256>>>(x_p, g1_Ws, g1_b, agg, h_p);

    // ---- M_hat = h_r @ h_p^T (per batch) ----
    mhat_kernel<<<Bq, 128>>>(h_r, h_p, Mhat);

    // ---- consensus iterations ----
    for (int it = 0; it < 3; ++it) {
        // M = softmax(M_hat); iter 0 also writes M_0 output
        softmax_kernel<<<1024, 256>>>(Mhat, M, (it == 0) ? out : (float*)nullptr);

        // rf_r = jax.random.normal(fold_in(key(42), it), (B,N,RIN))
        unsigned k0, k1;
        host_threefry(0u, 42u, 0u, (unsigned)it, &k0, &k1);
        rfgen_kernel<<<RFCNT/256, 256>>>(rf_r, k0, k1);

        // rf_p = M^T @ rf_r
        rfp_kernel<<<Bq, 128>>>(M, rf_r, rf_p);

        // o_r = gnn2(rf_r, r-graph); a_r = o_r@W1 + b1
        zero_kernel<<<2048, 256>>>(agg, NTOT*64);
        edge_kernel<32><<<1024, 256>>>(rf_r, ei_r, ef_r, g2_Wm, g2_We, agg);
        node_kernel<32, true><<<256, 256>>>(rf_r, g2_Ws, g2_b, agg, o);
        node_kernel<64, false><<<256, 256>>>(o, W1, b1, nullptr, a_r);

        // o_p = gnn2(rf_p, p-graph); a_p = o_p@W1
        zero_kernel<<<2048, 256>>>(agg, NTOT*64);
        edge_kernel<32><<<1024, 256>>>(rf_p, ei_p, ef_p, g2_Wm, g2_We, agg);
        node_kernel<32, true><<<256, 256>>>(rf_p, g2_Ws, g2_b, agg, o);
        node_kernel<64, false><<<256, 256>>>(o, W1, nullptr, nullptr, a_p);

        // M_hat += relu(a_r[r]-a_p[p]) @ W2 + b2
        upd_kernel<<<Bq, 256, 2*Nq*ROUTq*4>>>(a_r, a_p, W2, b2, Mhat);
    }

    // ---- M_T output ----
    softmax_kernel<<<1024, 256>>>(Mhat, out + M_ELEMS, nullptr);
}

// round 16
// speedup vs baseline: 1.7977x; 1.7937x over previous
#include <cuda_runtime.h>
#include <math.h>

// ---------------- problem constants ----------------
#define Bq     64
#define Nq     128
#define NTOT   8192          // B*N
#define RINq   32
#define ROUTq  64
#define DEMBq  64
#define FINq   64
#define FEq    16
#define NEDGE  65536
#define RFCNT  (NTOT*RINq)   // 262144
#define M_ELEMS (Bq*Nq*Nq)   // 1048576

// ---------------- scratch (device globals; no runtime alloc) ----------------
__device__ float g_em1_r[NEDGE*64];   // ef_r @ g1_We
__device__ float g_em1_p[NEDGE*64];   // ef_p @ g1_We
__device__ float g_em2_r[NEDGE*64];   // ef_r @ g2_We (reused 3 iters)
__device__ float g_em2_p[NEDGE*64];   // ef_p @ g2_We (reused 3 iters)
__device__ float g_xm_r [NTOT*64];
__device__ float g_xm_p [NTOT*64];
__device__ float g_agg_r[NTOT*64];
__device__ float g_agg_p[NTOT*64];
__device__ float g_h_r  [NTOT*DEMBq];
__device__ float g_h_p  [NTOT*DEMBq];
__device__ float g_Mhat [M_ELEMS];
__device__ float g_M    [M_ELEMS];
__device__ float g_rf_r [NTOT*RINq];
__device__ float g_rf_p [NTOT*RINq];
__device__ float g_a_r  [NTOT*64];
__device__ float g_a_p  [NTOT*64];

// ---------------- em = ef @ We (per edge), 4 jobs via blockIdx.y ----------------
__global__ void em_kernel(const float* __restrict__ ef_r, const float* __restrict__ ef_p,
                          const float* __restrict__ We1,  const float* __restrict__ We2,
                          float* __restrict__ em1_r, float* __restrict__ em1_p,
                          float* __restrict__ em2_r, float* __restrict__ em2_p)
{
    const float* ef; const float* We; float* em;
    switch (blockIdx.y) {
        case 0: ef = ef_r; We = We1; em = em1_r; break;
        case 1: ef = ef_p; We = We1; em = em1_p; break;
        case 2: ef = ef_r; We = We2; em = em2_r; break;
        default: ef = ef_p; We = We2; em = em2_p; break;
    }
    __shared__ float2 sWe[FEq * 32];
    for (int i = threadIdx.x; i < FEq * 32; i += blockDim.x) {
        int c = i >> 5, j = i & 31;
        sWe[i] = make_float2(We[c*64 + j], We[c*64 + 32 + j]);
    }
    __syncthreads();

    const int lane  = threadIdx.x & 31;
    const int warp  = threadIdx.x >> 5;
    const int nwarp = blockDim.x >> 5;

    for (int e = blockIdx.x * nwarp + warp; e < NEDGE; e += gridDim.x * nwarp) {
        float efv = __ldg(ef + e*FEq + (lane & 15));
        float acc0 = 0.0f, acc1 = 0.0f;
        #pragma unroll
        for (int c = 0; c < FEq; ++c) {
            float ec = __shfl_sync(0xffffffffu, efv, c);
            float2 w = sWe[c*32 + lane];
            acc0 = fmaf(ec, w.x, acc0);
            acc1 = fmaf(ec, w.y, acc1);
        }
        em[e*64 + lane]      = acc0;
        em[e*64 + 32 + lane] = acc1;
    }
}

// ---------------- xm = x @ Wm (per node) + zero agg; 2 jobs via blockIdx.y ----------------
template<int FIN_T>
__global__ void xm_kernel(const float* __restrict__ xA, const float* __restrict__ xB,
                          const float* __restrict__ Wm,
                          float* __restrict__ xmA, float* __restrict__ xmB,
                          float* __restrict__ aggA, float* __restrict__ aggB)
{
    const float* x  = blockIdx.y ? xB  : xA;
    float* xm       = blockIdx.y ? xmB : xmA;
    float* agg      = blockIdx.y ? aggB : aggA;

    __shared__ float2 sW[FIN_T * 32];
    for (int i = threadIdx.x; i < FIN_T * 32; i += blockDim.x) {
        int k = i >> 5, j = i & 31;
        sW[i] = make_float2(Wm[k*64 + j], Wm[k*64 + 32 + j]);
    }
    __syncthreads();

    const int lane  = threadIdx.x & 31;
    const int warp  = threadIdx.x >> 5;
    const int nwarp = blockDim.x >> 5;

    for (int n = blockIdx.x * nwarp + warp; n < NTOT; n += gridDim.x * nwarp) {
        float xv0 = __ldg(x + n*FIN_T + lane);
        float xv1 = (FIN_T > 32) ? __ldg(x + n*FIN_T + 32 + lane) : 0.0f;
        float acc0 = 0.0f, acc1 = 0.0f;
        #pragma unroll
        for (int k = 0; k < FIN_T; ++k) {
            float xk = __shfl_sync(0xffffffffu, (k < 32) ? xv0 : xv1, k & 31);
            float2 w = sW[k*32 + lane];
            acc0 = fmaf(xk, w.x, acc0);
            acc1 = fmaf(xk, w.y, acc1);
        }
        xm[n*64 + lane]       = acc0;
        xm[n*64 + 32 + lane]  = acc1;
        agg[n*64 + lane]      = 0.0f;
        agg[n*64 + 32 + lane] = 0.0f;
    }
}

// ---------------- fused edge scatter for both graphs ----------------
// agg[dst] += relu(xm[src] + em[e]) ; warp per edge, lane covers 2 cols (float2)
__global__ void edge_kernel(const float* __restrict__ xm_r, const int* __restrict__ ei_r,
                            const float* __restrict__ em_r, float* __restrict__ agg_r,
                            const float* __restrict__ xm_p, const int* __restrict__ ei_p,
                            const float* __restrict__ em_p, float* __restrict__ agg_p)
{
    const int lane  = threadIdx.x & 31;
    const int warp  = threadIdx.x >> 5;
    const int nwarp = blockDim.x >> 5;

    for (int ge = blockIdx.x * nwarp + warp; ge < 2*NEDGE; ge += gridDim.x * nwarp) {
        const float* xm; const int* ei; const float* em; float* agg;
        int e;
        if (ge < NEDGE) { xm = xm_r; ei = ei_r; em = em_r; agg = agg_r; e = ge; }
        else            { xm = xm_p; ei = ei_p; em = em_p; agg = agg_p; e = ge - NEDGE; }
        int s = __ldg(ei + e);
        int d = __ldg(ei + NEDGE + e);
        float2 xv = *(const float2*)(xm + s*64 + lane*2);
        float2 ev = *(const float2*)(em + e*64 + lane*2);
        float m0 = fmaxf(xv.x + ev.x, 0.0f);
        float m1 = fmaxf(xv.y + ev.y, 0.0f);
        float* dp = agg + d*64 + lane*2;
        atomicAdd(dp,     m0);
        atomicAdd(dp + 1, m1);
    }
}

// ---------------- node kernel (gnn1): h = relu(x @ Ws + agg + b); 2 jobs ----------------
template<int FIN_T>
__global__ void node1_kernel(const float* __restrict__ xA, const float* __restrict__ aggA, float* __restrict__ outA,
                             const float* __restrict__ xB, const float* __restrict__ aggB, float* __restrict__ outB,
                             const float* __restrict__ Ws, const float* __restrict__ bias)
{
    const float* x   = blockIdx.y ? xB   : xA;
    const float* agg = blockIdx.y ? aggB : aggA;
    float* out       = blockIdx.y ? outB : outA;

    __shared__ float2 sW[FIN_T * 32];
    __shared__ float  sb[64];
    for (int i = threadIdx.x; i < FIN_T * 32; i += blockDim.x) {
        int k = i >> 5, j = i & 31;
        sW[i] = make_float2(Ws[k*64 + j], Ws[k*64 + 32 + j]);
    }
    if (threadIdx.x < 64) sb[threadIdx.x] = bias[threadIdx.x];
    __syncthreads();

    const int lane  = threadIdx.x & 31;
    const int warp  = threadIdx.x >> 5;
    const int nwarp = blockDim.x >> 5;

    for (int n = blockIdx.x * nwarp + warp; n < NTOT; n += gridDim.x * nwarp) {
        float xv0 = __ldg(x + n*FIN_T + lane);
        float xv1 = (FIN_T > 32) ? __ldg(x + n*FIN_T + 32 + lane) : 0.0f;
        float acc0 = sb[lane], acc1 = sb[lane + 32];
        #pragma unroll
        for (int k = 0; k < FIN_T; ++k) {
            float xk = __shfl_sync(0xffffffffu, (k < 32) ? xv0 : xv1, k & 31);
            float2 w = sW[k*32 + lane];
            acc0 = fmaf(xk, w.x, acc0);
            acc1 = fmaf(xk, w.y, acc1);
        }
        acc0 = fmaxf(acc0 + agg[n*64 + lane],      0.0f);
        acc1 = fmaxf(acc1 + agg[n*64 + 32 + lane], 0.0f);
        out[n*64 + lane]      = acc0;
        out[n*64 + 32 + lane] = acc1;
    }
}

// ---------------- node kernel (gnn2) fused with W1: a = relu(x@Ws+agg+b)@W1 (+b1) ----------------
__global__ void node2_kernel(const float* __restrict__ xA, const float* __restrict__ aggA, float* __restrict__ outA,
                             const float* __restrict__ xB, const float* __restrict__ aggB, float* __restrict__ outB,
                             const float* __restrict__ Ws, const float* __restrict__ bias,
                             const float* __restrict__ W1, const float* __restrict__ b1)
{
    const float* x   = blockIdx.y ? xB   : xA;
    const float* agg = blockIdx.y ? aggB : aggA;
    float* out       = blockIdx.y ? outB : outA;
    const bool useB1 = (blockIdx.y == 0);

    __shared__ float2 sWs[RINq * 32];   // 8 KB
    __shared__ float2 sW1[64 * 32];     // 16 KB
    __shared__ float  sb[64];
    __shared__ float  sb1[64];
    for (int i = threadIdx.x; i < RINq * 32; i += blockDim.x) {
        int k = i >> 5, j = i & 31;
        sWs[i] = make_float2(Ws[k*64 + j], Ws[k*64 + 32 + j]);
    }
    for (int i = threadIdx.x; i < 64 * 32; i += blockDim.x) {
        int k = i >> 5, j = i & 31;
        sW1[i] = make_float2(W1[k*64 + j], W1[k*64 + 32 + j]);
    }
    if (threadIdx.x < 64) {
        sb[threadIdx.x]  = bias[threadIdx.x];
        sb1[threadIdx.x] = useB1 ? b1[threadIdx.x] : 0.0f;
    }
    __syncthreads();

    const int lane  = threadIdx.x & 31;
    const int warp  = threadIdx.x >> 5;
    const int nwarp = blockDim.x >> 5;

    for (int n = blockIdx.x * nwarp + warp; n < NTOT; n += gridDim.x * nwarp) {
        float xv0 = __ldg(x + n*RINq + lane);
        float acc0 = sb[lane], acc1 = sb[lane + 32];
        #pragma unroll
        for (int k = 0; k < RINq; ++k) {
            float xk = __shfl_sync(0xffffffffu, xv0, k);
            float2 w = sWs[k*32 + lane];
            acc0 = fmaf(xk, w.x, acc0);
            acc1 = fmaf(xk, w.y, acc1);
        }
        float o0 = fmaxf(acc0 + agg[n*64 + lane],      0.0f);
        float o1 = fmaxf(acc1 + agg[n*64 + 32 + lane], 0.0f);
        // a = o @ W1 (+ b1)
        float a0 = sb1[lane], a1 = sb1[lane + 32];
        #pragma unroll
        for (int k = 0; k < 64; ++k) {
            float ok = __shfl_sync(0xffffffffu, (k < 32) ? o0 : o1, k & 31);
            float2 w = sW1[k*32 + lane];
            a0 = fmaf(ok, w.x, a0);
            a1 = fmaf(ok, w.y, a1);
        }
        out[n*64 + lane]      = a0;
        out[n*64 + 32 + lane] = a1;
    }
}

// ---------------- M_hat = h_r @ h_p^T per batch (split p-halves over blockIdx.y) ----------------
__global__ void mhat_kernel(const float* __restrict__ hr,
                            const float* __restrict__ hp,
                            float* __restrict__ Mhat)
{
    __shared__ float sHp[64 * DEMBq];   // 16 KB: 64 p-rows
    int b = blockIdx.x;
    int half = blockIdx.y;
    const float* hpb = hp + (b * Nq + half * 64) * DEMBq;
    for (int i = threadIdx.x; i < 64 * DEMBq; i += blockDim.x) sHp[i] = hpb[i];
    __syncthreads();

    int r = threadIdx.x;                 // 128 threads, one r row each
    float xr[DEMBq];
    const float* hrr = hr + (b*Nq + r) * DEMBq;
    #pragma unroll
    for (int k = 0; k < DEMBq; ++k) xr[k] = hrr[k];
    float* mrow = Mhat + (b*Nq + r) * Nq + half * 64;
    for (int p = 0; p < 64; ++p) {
        float acc = 0.0f;
        #pragma unroll
        for (int k = 0; k < DEMBq; ++k) acc = fmaf(xr[k], sHp[p*DEMBq + k], acc);
        mrow[p] = acc;
    }
}

// ---------------- row softmax (warp per row of 128) ----------------
__global__ void softmax_kernel(const float* __restrict__ src,
                               float* __restrict__ dstA,
                               float* __restrict__ dstB)
{
    int row  = blockIdx.x * (blockDim.x >> 5) + (threadIdx.x >> 5);
    int lane = threadIdx.x & 31;
    if (row >= NTOT) return;
    const float* s = src + row * Nq;
    float v0 = s[lane], v1 = s[lane+32], v2 = s[lane+64], v3 = s[lane+96];
    float mx = fmaxf(fmaxf(v0, v1), fmaxf(v2, v3));
    #pragma unroll
    for (int o = 16; o > 0; o >>= 1) mx = fmaxf(mx, __shfl_xor_sync(0xffffffffu, mx, o));
    v0 = expf(v0 - mx); v1 = expf(v1 - mx); v2 = expf(v2 - mx); v3 = expf(v3 - mx);
    float sm = v0 + v1 + v2 + v3;
    #pragma unroll
    for (int o = 16; o > 0; o >>= 1) sm += __shfl_xor_sync(0xffffffffu, sm, o);
    float inv = 1.0f / sm;
    float* dA = dstA + row * Nq;
    dA[lane] = v0*inv; dA[lane+32] = v1*inv; dA[lane+64] = v2*inv; dA[lane+96] = v3*inv;
    if (dstB) {
        float* dB = dstB + row * Nq;
        dB[lane] = v0*inv; dB[lane+32] = v1*inv; dB[lane+64] = v2*inv; dB[lane+96] = v3*inv;
    }
}

// ---------------- threefry + jax.random.normal reproduction ----------------
__device__ __forceinline__ unsigned rotl32d(unsigned v, int s) { return (v << s) | (v >> (32 - s)); }

__device__ __forceinline__ float erfinv_xla(float x)
{
    float w = -log1pf(-x * x);
    float p;
    if (w < 5.0f) {
        w = w - 2.5f;
        p = 2.81022636e-08f;
        p = fmaf(p, w, 3.43273939e-07f);
        p = fmaf(p, w, -3.5233877e-06f);
        p = fmaf(p, w, -4.39150654e-06f);
        p = fmaf(p, w, 0.00021858087f);
        p = fmaf(p, w, -0.00125372503f);
        p = fmaf(p, w, -0.00417768164f);
        p = fmaf(p, w, 0.246640727f);
        p = fmaf(p, w, 1.50140941f);
    } else {
        w = sqrtf(w) - 3.0f;
        p = -0.000200214257f;
        p = fmaf(p, w, 0.000100950558f);
        p = fmaf(p, w, 0.00134934322f);
        p = fmaf(p, w, -0.00367342844f);
        p = fmaf(p, w, 0.00573950773f);
        p = fmaf(p, w, -0.0076224613f);
        p = fmaf(p, w, 0.00943887047f);
        p = fmaf(p, w, 1.00167406f);
        p = fmaf(p, w, 2.83297682f);
    }
    return p * x;
}

__device__ __forceinline__ float bits_to_normal(unsigned w)
{
    const float LO = -0.99999994f;          // nextafter(-1, 0)
    const float SCALE = 1.0f - LO;
    float u = __uint_as_float((w >> 9) | 0x3f800000u) - 1.0f;
    float a = fmaxf(fmaf(u, SCALE, LO), LO);
    return 1.41421356237f * erfinv_xla(a);
}

// Partitionable threefry: counter (0, i); word = x0 ^ x1.
__global__ void rfgen_kernel(float* __restrict__ rf, unsigned k0, unsigned k1)
{
    int i = blockIdx.x * blockDim.x + threadIdx.x;
    if (i >= RFCNT) return;
    unsigned ks2 = k0 ^ k1 ^ 0x1BD11BDAu;
    unsigned x0 = k0;
    unsigned x1 = (unsigned)i + k1;
    #define TFR(r) { x0 += x1; x1 = rotl32d(x1, r); x1 ^= x0; }
    TFR(13) TFR(15) TFR(26) TFR(6)   x0 += k1;  x1 += ks2 + 1u;
    TFR(17) TFR(29) TFR(16) TFR(24)  x0 += ks2; x1 += k0 + 2u;
    TFR(13) TFR(15) TFR(26) TFR(6)   x0 += k0;  x1 += k1 + 3u;
    TFR(17) TFR(29) TFR(16) TFR(24)  x0 += k1;  x1 += ks2 + 4u;
    TFR(13) TFR(15) TFR(26) TFR(6)   x0 += ks2; x1 += k0 + 5u;
    #undef TFR
    rf[i] = bits_to_normal(x0 ^ x1);
}

// ---------------- rf_p[b,p,:] = sum_r M[b,r,p] * rf_r[b,r,:]; RIN-halves over blockIdx.y ----------------
__global__ void rfp_kernel(const float* __restrict__ M,
                           const float* __restrict__ rfr,
                           float* __restrict__ rfp)
{
    __shared__ float sR[Nq * 16];   // 8 KB
    int b = blockIdx.x;
    int half = blockIdx.y;
    const float* Mb = M + b * Nq * Nq;
    for (int idx = threadIdx.x; idx < Nq * 16; idx += blockDim.x) {
        int r = idx >> 4, i = idx & 15;
        sR[idx] = rfr[(b*Nq + r) * RINq + half*16 + i];
    }
    __syncthreads();

    int p = threadIdx.x;              // 128 threads
    float acc[16];
    #pragma unroll
    for (int i = 0; i < 16; ++i) acc[i] = 0.0f;
    for (int r = 0; r < Nq; ++r) {
        float m = Mb[r * Nq + p];     // coalesced across threads
        #pragma unroll
        for (int i = 0; i < 16; ++i) acc[i] = fmaf(m, sR[r*16 + i], acc[i]);
    }
    float* ob = rfp + (b*Nq + p) * RINq + half*16;
    #pragma unroll
    for (int i = 0; i < 16; ++i) ob[i] = acc[i];
}

// ---------------- consensus update ----------------
// Mhat[b,r,p] += sum_k relu(a_r[b,r,k] - a_p[b,p,k]) * W2[k] + b2
// grid (64 batches, 4 row-quarters); coalesced ap load + stride-129 smem transpose.
__global__ void upd_kernel(const float* __restrict__ ar,
                           const float* __restrict__ ap,
                           const float* __restrict__ W2,
                           const float* __restrict__ b2p,
                           float* __restrict__ Mhat)
{
    __shared__ float sApT[64 * 129];   // [k][p], padded stride 129 (33 KB)
    __shared__ float sAr [32 * 64];    // [r_local][k] (8 KB)
    __shared__ float sW2 [64];

    int b = blockIdx.x;
    int q = blockIdx.y;                // row quarter
    const float* apb = ap + b * Nq * ROUTq;
    const float* arb = ar + (b * Nq + q * 32) * ROUTq;

    // coalesced load of ap (p-major), transposed store with padded stride
    for (int i = threadIdx.x; i < Nq * ROUTq; i += blockDim.x) {
        int p = i >> 6, k = i & 63;
        sApT[k*129 + p] = apb[i];
    }
    for (int i = threadIdx.x; i < 32 * ROUTq; i += blockDim.x) sAr[i] = arb[i];
    if (threadIdx.x < 64) sW2[threadIdx.x] = W2[threadIdx.x];
    __syncthreads();

    float b2 = b2p[0];
    int lane = threadIdx.x & 31;
    int warp = threadIdx.x >> 5;       // 8 warps, 4 rows each

    for (int rr = 0; rr < 4; ++rr) {
        int rl = warp * 4 + rr;
        const float* arow = sAr + rl * ROUTq;
        float acc0 = 0.f, acc1 = 0.f, acc2 = 0.f, acc3 = 0.f;
        #pragma unroll 8
        for (int k = 0; k < ROUTq; ++k) {
            float av = arow[k];
            float w  = sW2[k];
            const float* aprow = sApT + k * 129;
            acc0 = fmaf(fmaxf(av - aprow[lane     ], 0.f), w, acc0);
            acc1 = fmaf(fmaxf(av - aprow[lane + 32], 0.f), w, acc1);
            acc2 = fmaf(fmaxf(av - aprow[lane + 64], 0.f), w, acc2);
            acc3 = fmaf(fmaxf(av - aprow[lane + 96], 0.f), w, acc3);
        }
        float* mr = Mhat + (b*Nq + q*32 + rl) * Nq;
        mr[lane]      += acc0 + b2;
        mr[lane + 32] += acc1 + b2;
        mr[lane + 64] += acc2 + b2;
        mr[lane + 96] += acc3 + b2;
    }
}

// ---------------- host threefry (key fold_in; classic 2-element scheme) ----------------
static void host_threefry(unsigned k0, unsigned k1, unsigned c0, unsigned c1,
                          unsigned* o0, unsigned* o1)
{
    unsigned ks2 = k0 ^ k1 ^ 0x1BD11BDAu;
    unsigned x0 = c0 + k0, x1 = c1 + k1;
    #define HTFR(r) { x0 += x1; x1 = (x1 << (r)) | (x1 >> (32 - (r))); x1 ^= x0; }
    HTFR(13) HTFR(15) HTFR(26) HTFR(6)   x0 += k1;  x1 += ks2 + 1u;
    HTFR(17) HTFR(29) HTFR(16) HTFR(24)  x0 += ks2; x1 += k0 + 2u;
    HTFR(13) HTFR(15) HTFR(26) HTFR(6)   x0 += k0;  x1 += k1 + 3u;
    HTFR(17) HTFR(29) HTFR(16) HTFR(24)  x0 += k1;  x1 += ks2 + 4u;
    HTFR(13) HTFR(15) HTFR(26) HTFR(6)   x0 += ks2; x1 += k0 + 5u;
    #undef HTFR
    *o0 = x0; *o1 = x1;
}

// ---------------- orchestration ----------------
extern "C" void kernel_launch(void* const* d_in, const int* in_sizes, int n_in,
                              void* d_out, int out_size)
{
    const float* x_r   = (const float*)d_in[0];
    const int*   ei_r  = (const int*)  d_in[1];
    const float* ef_r  = (const float*)d_in[2];
    const float* x_p   = (const float*)d_in[3];
    const int*   ei_p  = (const int*)  d_in[4];
    const float* ef_p  = (const float*)d_in[5];
    // d_in[6], d_in[7]: masks (all True) — unused
    const float* g1_Ws = (const float*)d_in[8];
    const float* g1_Wm = (const float*)d_in[9];
    const float* g1_We = (const float*)d_in[10];
    const float* g1_b  = (const float*)d_in[11];
    const float* g2_Ws = (const float*)d_in[12];
    const float* g2_Wm = (const float*)d_in[13];
    const float* g2_We = (const float*)d_in[14];
    const float* g2_b  = (const float*)d_in[15];
    const float* W1    = (const float*)d_in[16];
    const float* b1    = (const float*)d_in[17];
    const float* W2    = (const float*)d_in[18];
    const float* b2    = (const float*)d_in[19];
    float* out = (float*)d_out;

    float *em1_r, *em1_p, *em2_r, *em2_p, *xm_r, *xm_p, *agg_r, *agg_p;
    float *h_r, *h_p, *Mhat, *M, *rf_r, *rf_p, *a_r, *a_p;
    cudaGetSymbolAddress((void**)&em1_r, g_em1_r);
    cudaGetSymbolAddress((void**)&em1_p, g_em1_p);
    cudaGetSymbolAddress((void**)&em2_r, g_em2_r);
    cudaGetSymbolAddress((void**)&em2_p, g_em2_p);
    cudaGetSymbolAddress((void**)&xm_r,  g_xm_r);
    cudaGetSymbolAddress((void**)&xm_p,  g_xm_p);
    cudaGetSymbolAddress((void**)&agg_r, g_agg_r);
    cudaGetSymbolAddress((void**)&agg_p, g_agg_p);
    cudaGetSymbolAddress((void**)&h_r,   g_h_r);
    cudaGetSymbolAddress((void**)&h_p,   g_h_p);
    cudaGetSymbolAddress((void**)&Mhat,  g_Mhat);
    cudaGetSymbolAddress((void**)&M,     g_M);
    cudaGetSymbolAddress((void**)&rf_r,  g_rf_r);
    cudaGetSymbolAddress((void**)&rf_p,  g_rf_p);
    cudaGetSymbolAddress((void**)&a_r,   g_a_r);
    cudaGetSymbolAddress((void**)&a_p,   g_a_p);

    // ---- precompute all edge-feature messages (em2 reused 3 iterations) ----
    em_kernel<<<dim3(256, 4), 256>>>(ef_r, ef_p, g1_We, g2_We, em1_r, em1_p, em2_r, em2_p);

    // ---- gnn_1 on both graphs -> h_r, h_p ----
    xm_kernel<64><<<dim3(64, 2), 256>>>(x_r, x_p, g1_Wm, xm_r, xm_p, agg_r, agg_p);
    edge_kernel<<<2048, 256>>>(xm_r, ei_r, em1_r, agg_r, xm_p, ei_p, em1_p, agg_p);
    node1_kernel<64><<<dim3(64, 2), 256>>>(x_r, agg_r, h_r, x_p, agg_p, h_p, g1_Ws, g1_b);

    // ---- M_hat = h_r @ h_p^T ----
    mhat_kernel<<<dim3(Bq, 2), 128>>>(h_r, h_p, Mhat);

    // ---- consensus iterations ----
    for (int it = 0; it < 3; ++it) {
        softmax_kernel<<<1024, 256>>>(Mhat, M, (it == 0) ? out : (float*)nullptr);

        unsigned k0, k1;
        host_threefry(0u, 42u, 0u, (unsigned)it, &k0, &k1);
        rfgen_kernel<<<RFCNT/256, 256>>>(rf_r, k0, k1);

        rfp_kernel<<<dim3(Bq, 2), 128>>>(M, rf_r, rf_p);

        // gnn2 on both graphs, fused with @W1 (+b1 on r side)
        xm_kernel<32><<<dim3(64, 2), 256>>>(rf_r, rf_p, g2_Wm, xm_r, xm_p, agg_r, agg_p);
        edge_kernel<<<2048, 256>>>(xm_r, ei_r, em2_r, agg_r, xm_p, ei_p, em2_p, agg_p);
        node2_kernel<<<dim3(64, 2), 256>>>(rf_r, agg_r, a_r, rf_p, agg_p, a_p,
                                           g2_Ws, g2_b, W1, b1);

        upd_kernel<<<dim3(Bq, 4), 256>>>(a_r, a_p, W2, b2, Mhat);
    }

    // ---- M_T output ----
    softmax_kernel<<<1024, 256>>>(Mhat, out + M_ELEMS, nullptr);
}